// round 6
// baseline (speedup 1.0000x reference)
#include <cuda_runtime.h>

#define PNUM 32
#define INF  7
#define D2   64
#define OUTF 4096   // 2*D2*PNUM floats per voxel
#define VPB  8      // voxels per block

__global__ __launch_bounds__(128, 8)
void vfe_kernel(const float* __restrict__ x,
                const float* __restrict__ W,
                const float* __restrict__ bias,
                float* __restrict__ out,
                int B)
{
    __shared__ float sx[VPB][PNUM * 8];  // all voxels staged, rows padded to 8
    __shared__ float sglob[VPB][D2];     // per-voxel global vectors

    const int t   = threadIdx.x;
    const int dg  = t & 15;              // dim group: dims [4*dg, 4*dg+4)
    const int pgr = t >> 4;              // point group: points [4*pgr, 4*pgr+4)

    // Per-thread weights + bias in registers, reused across all voxels.
    float w[4][INF], bb[4];
    #pragma unroll
    for (int k = 0; k < 4; k++) {
        const int d = dg * 4 + k;
        bb[k] = bias[d];
        #pragma unroll
        for (int i = 0; i < INF; i++) w[k][i] = W[d * INF + i];
    }

    const int v0   = blockIdx.x * VPB;
    const int nvox = min(VPB, B - v0);
    float* sxf = &sx[0][0];

    // Front-loaded read burst: all voxels' x (1792 floats) in one coalesced pass.
    // After this the block issues ONLY writes (minus tiny LDS) -> no R/W mixing.
    {
        const float* xv = x + (size_t)v0 * (PNUM * INF);
        const int lim = nvox * PNUM * INF;
        #pragma unroll
        for (int q = 0; q < 14; q++) {
            const int idx = t + q * 128;          // 0..1791
            if (idx < lim) {
                const float val = __ldcs(xv + idx);
                const int r = idx / INF;          // point row 0..255
                sxf[r * 8 + (idx - r * INF)] = val;
            }
        }
    }
    __syncthreads();

    // ---- Phase 1: locals + maxes for ALL voxels (no barriers) ----
    #pragma unroll 1
    for (int it = 0; it < nvox; it++) {
        float* ov = out + (size_t)(v0 + it) * OUTF;
        const float* sxv = &sx[it][0];

        #pragma unroll
        for (int j = 0; j < 4; j++) {
            const int p = pgr * 4 + j;
            const float4 a0 = *(const float4*)(sxv + p * 8);
            const float4 a1 = *(const float4*)(sxv + p * 8 + 4);

            float acc[4];
            #pragma unroll
            for (int k = 0; k < 4; k++) {
                float a = bb[k];
                a = fmaf(a0.x, w[k][0], a);
                a = fmaf(a0.y, w[k][1], a);
                a = fmaf(a0.z, w[k][2], a);
                a = fmaf(a0.w, w[k][3], a);
                a = fmaf(a1.x, w[k][4], a);
                a = fmaf(a1.y, w[k][5], a);
                a = fmaf(a1.z, w[k][6], a);
                acc[k] = a;
            }

            // Local half of row p: coalesced streaming STG.128.
            __stcs((float4*)(ov + p * 128 + dg * 4),
                   make_float4(acc[0], acc[1], acc[2], acc[3]));

            // Half-row max over this 8-lane group (dims [32h,32h+32) of point p).
            float m = fmaxf(fmaxf(acc[0], acc[1]), fmaxf(acc[2], acc[3]));
            m = fmaxf(m, __shfl_xor_sync(0xffffffffu, m, 1));
            m = fmaxf(m, __shfl_xor_sync(0xffffffffu, m, 2));
            m = fmaxf(m, __shfl_xor_sync(0xffffffffu, m, 4));
            if ((t & 7) == 0)
                sglob[it][2 * p + ((t >> 3) & 1)] = m;
        }
    }

    __syncthreads();   // the ONE barrier: publish all global vectors

    // ---- Phase 2: pure broadcast-store burst (no compute, no sync) ----
    #pragma unroll 1
    for (int it = 0; it < nvox; it++) {
        float* ov = out + (size_t)(v0 + it) * OUTF;
        const float4 gv = *(const float4*)(&sglob[it][dg * 4]);
        #pragma unroll
        for (int j = 0; j < 4; j++) {
            const int p = pgr * 4 + j;
            __stcs((float4*)(ov + p * 128 + 64 + dg * 4), gv);
        }
    }
}

extern "C" void kernel_launch(void* const* d_in, const int* in_sizes, int n_in,
                              void* d_out, int out_size)
{
    const float* x = (const float*)d_in[0];
    const float* W = (const float*)d_in[1];
    const float* b = (const float*)d_in[2];
    float* out     = (float*)d_out;

    const int B = in_sizes[0] / (PNUM * INF);       // 32768
    const int grid = (B + VPB - 1) / VPB;           // 4096
    vfe_kernel<<<grid, 128>>>(x, W, b, out, B);
}

// round 7
// speedup vs baseline: 1.0221x; 1.0221x over previous
#include <cuda_runtime.h>

#define PNUM 32
#define INF  7
#define D2   64
#define OUTF 4096   // 2*D2*PNUM floats per voxel
#define VPB  4      // voxels per block

__global__ __launch_bounds__(128, 8)
void vfe_kernel(const float* __restrict__ x,
                const float* __restrict__ W,
                const float* __restrict__ bias,
                float* __restrict__ out,
                int B)
{
    __shared__ float sx[VPB][PNUM * 8];  // all voxels staged, rows padded to 8
    __shared__ float sglob[2][D2];       // parity double-buffered global vector

    const int t   = threadIdx.x;
    const int dg  = t & 15;              // dim group: dims [4*dg, 4*dg+4)
    const int pgr = t >> 4;              // point group: points [4*pgr, 4*pgr+4)

    // Per-thread weights + bias in registers, reused across all voxels.
    float w[4][INF], bb[4];
    #pragma unroll
    for (int k = 0; k < 4; k++) {
        const int d = dg * 4 + k;
        bb[k] = bias[d];
        #pragma unroll
        for (int i = 0; i < INF; i++) w[k][i] = W[d * INF + i];
    }

    const int v0   = blockIdx.x * VPB;
    const int nvox = min(VPB, B - v0);
    float* sxf = &sx[0][0];

    // Front-loaded read burst: all voxels' x (896 floats) in one coalesced pass.
    {
        const float* xv = x + (size_t)v0 * (PNUM * INF);
        const int lim = nvox * PNUM * INF;
        #pragma unroll
        for (int q = 0; q < 7; q++) {
            const int idx = t + q * 128;          // 0..895
            if (idx < lim) {
                const float val = __ldcs(xv + idx);
                const int r = idx / INF;          // point row 0..127
                sxf[r * 8 + (idx - r * INF)] = val;
            }
        }
    }
    __syncthreads();

    // Phase 1 for one voxel: FMAs, coalesced local stores, half-row maxes.
    auto phase1 = [&](int it) {
        float* ov = out + (size_t)(v0 + it) * OUTF;
        const float* sxv = &sx[it][0];
        #pragma unroll
        for (int j = 0; j < 4; j++) {
            const int p = pgr * 4 + j;
            const float4 a0 = *(const float4*)(sxv + p * 8);
            const float4 a1 = *(const float4*)(sxv + p * 8 + 4);

            float acc[4];
            #pragma unroll
            for (int k = 0; k < 4; k++) {
                float a = bb[k];
                a = fmaf(a0.x, w[k][0], a);
                a = fmaf(a0.y, w[k][1], a);
                a = fmaf(a0.z, w[k][2], a);
                a = fmaf(a0.w, w[k][3], a);
                a = fmaf(a1.x, w[k][4], a);
                a = fmaf(a1.y, w[k][5], a);
                a = fmaf(a1.z, w[k][6], a);
                acc[k] = a;
            }

            __stcs((float4*)(ov + p * 128 + dg * 4),
                   make_float4(acc[0], acc[1], acc[2], acc[3]));

            float m = fmaxf(fmaxf(acc[0], acc[1]), fmaxf(acc[2], acc[3]));
            m = fmaxf(m, __shfl_xor_sync(0xffffffffu, m, 1));
            m = fmaxf(m, __shfl_xor_sync(0xffffffffu, m, 2));
            m = fmaxf(m, __shfl_xor_sync(0xffffffffu, m, 4));
            if ((t & 7) == 0)
                sglob[it & 1][2 * p + ((t >> 3) & 1)] = m;
        }
    };

    // Prologue: voxel 0 locals + maxes, publish.
    phase1(0);
    __syncthreads();

    // Pipelined steady state: issue gv load, overlap with next voxel's phase 1,
    // then emit broadcast stores; ONE barrier per voxel, no post-barrier bubble.
    #pragma unroll 1
    for (int it = 0; it < nvox; it++) {
        const float4 gv = *(const float4*)(&sglob[it & 1][dg * 4]);  // LDS issued early

        if (it + 1 < nvox)
            phase1(it + 1);          // independent work covers the LDS latency

        float* ov = out + (size_t)(v0 + it) * OUTF;
        #pragma unroll
        for (int j = 0; j < 4; j++) {
            const int p = pgr * 4 + j;
            __stcs((float4*)(ov + p * 128 + 64 + dg * 4), gv);
        }

        __syncthreads();   // publishes sglob[(it+1)&1]; orders parity-buffer reuse
    }
}

extern "C" void kernel_launch(void* const* d_in, const int* in_sizes, int n_in,
                              void* d_out, int out_size)
{
    const float* x = (const float*)d_in[0];
    const float* W = (const float*)d_in[1];
    const float* b = (const float*)d_in[2];
    float* out     = (float*)d_out;

    const int B = in_sizes[0] / (PNUM * INF);       // 32768
    const int grid = (B + VPB - 1) / VPB;           // 8192
    vfe_kernel<<<grid, 128>>>(x, W, b, out, B);
}